// round 4
// baseline (speedup 1.0000x reference)
#include <cuda_runtime.h>
#include <stdint.h>
#include <math.h>

#define N_NODES 100000
#define E_EDGES 3200000
#define C_IN 256
#define C1 64
#define C2 40

// ---------------- scratch (device globals; allocation-free) ----------------
__device__ __align__(16) float g_deg[N_NODES];
__device__ __align__(16) float g_dinv[N_NODES];
__device__ __align__(16) int   g_src[E_EDGES];
__device__ __align__(16) int   g_dst[E_EDGES];
__device__ __align__(16) float g_norm[E_EDGES];
__device__ __align__(16) float g_xw1[N_NODES * C1];   // x @ W1
__device__ __align__(16) float g_out1[N_NODES * C1];  // aggregated layer-1 pre-relu
__device__ __align__(16) float g_xw2[N_NODES * C2];   // relu(out1) @ W2
__device__ __align__(16) float g_out2[N_NODES * C2];  // aggregated layer-2 logits
__device__ int g_is64;   // 1 if edge_index buffer is int64, 0 if int32

// ---------------- dtype detection (int32 vs int64 edge buffer) -------------
// int64 little-endian: odd 32-bit words are hi-words == 0 (all ids < 2^31).
// int32: odd words are random node ids; 64 consecutive zeros ~ impossible.
__global__ void k_detect(const int* __restrict__ ei32) {
    if (blockIdx.x == 0 && threadIdx.x == 0) {
        int all0 = 1;
        for (int k = 0; k < 64; k++)
            if (ei32[2 * k + 1] != 0) { all0 = 0; break; }
        g_is64 = all0;
    }
}

__device__ __forceinline__ int load_src(const int* ei32, int e) {
    return g_is64 ? ei32[2 * e] : ei32[e];
}
__device__ __forceinline__ int load_dst(const int* ei32, int e) {
    return g_is64 ? ei32[2 * (E_EDGES + e)] : ei32[E_EDGES + e];
}

// ---------------- degree / norm precompute ----------------
__global__ void k_deg_init() {
    int i = blockIdx.x * blockDim.x + threadIdx.x;
    if (i < N_NODES) g_deg[i] = 1.0f;   // self loop
}

__global__ void k_deg_count(const int* __restrict__ ei32) {
    int e = blockIdx.x * blockDim.x + threadIdx.x;
    if (e >= E_EDGES) return;
    int d = load_dst(ei32, e);
    atomicAdd(&g_deg[d], 1.0f);
}

__global__ void k_dinv() {
    int i = blockIdx.x * blockDim.x + threadIdx.x;
    if (i < N_NODES) g_dinv[i] = rsqrtf(g_deg[i]);
}

__global__ void k_edge_prep(const int* __restrict__ ei32) {
    int e = blockIdx.x * blockDim.x + threadIdx.x;
    if (e >= E_EDGES) return;
    int s = load_src(ei32, e);
    int d = load_dst(ei32, e);
    g_src[e] = s;
    g_dst[e] = d;
    g_norm[e] = g_dinv[s] * g_dinv[d];
}

// ---------------- GEMM1: xw1 = x @ W1  ([N,256]x[256,64]) ----------------
__global__ void k_gemm1(const float* __restrict__ x, const float* __restrict__ W1) {
    __shared__ float xs[64][68];
    __shared__ float ws[64][64];
    int t = threadIdx.x;
    int rb = blockIdx.x * 64;
    int r = t >> 2, q = t & 3;

    float acc[16];
#pragma unroll
    for (int j = 0; j < 16; j++) acc[j] = 0.0f;

    for (int kc = 0; kc < C_IN; kc += 64) {
#pragma unroll
        for (int it = 0; it < 4; it++) {
            int i = t + 256 * it;
            int rr = i >> 4, cc = (i & 15) << 2;
            int row = rb + rr;
            float4 v = make_float4(0.f, 0.f, 0.f, 0.f);
            if (row < N_NODES)
                v = *(const float4*)(x + (long)row * C_IN + kc + cc);
            *(float4*)(&xs[rr][cc]) = v;
        }
#pragma unroll
        for (int it = 0; it < 4; it++) {
            int i = t + 256 * it;
            int kk = i >> 4, cc = (i & 15) << 2;
            *(float4*)(&ws[kk][cc]) = *(const float4*)(W1 + (kc + kk) * C1 + cc);
        }
        __syncthreads();

#pragma unroll
        for (int k = 0; k < 64; k++) {
            float xv = xs[r][k];
#pragma unroll
            for (int j4 = 0; j4 < 4; j4++) {
                float4 w4 = *(float4*)(&ws[k][q * 16 + j4 * 4]);
                acc[j4 * 4 + 0] += xv * w4.x;
                acc[j4 * 4 + 1] += xv * w4.y;
                acc[j4 * 4 + 2] += xv * w4.z;
                acc[j4 * 4 + 3] += xv * w4.w;
            }
        }
        __syncthreads();
    }

    int row = rb + r;
    if (row < N_NODES) {
#pragma unroll
        for (int j4 = 0; j4 < 4; j4++) {
            float4 o;
            o.x = acc[j4 * 4 + 0]; o.y = acc[j4 * 4 + 1];
            o.z = acc[j4 * 4 + 2]; o.w = acc[j4 * 4 + 3];
            *(float4*)(g_xw1 + (long)row * C1 + q * 16 + j4 * 4) = o;
        }
    }
}

// ---------------- init out1 = b1 + xw1 * dinv^2 (self loop) ----------------
__global__ void k_init1(const float* __restrict__ b1) {
    int i = blockIdx.x * blockDim.x + threadIdx.x;   // float4 index
    const int NV = N_NODES * (C1 / 4);
    if (i >= NV) return;
    int row = i >> 4;
    int c4 = i & 15;
    float dv = g_dinv[row];
    float sl = dv * dv;
    float4 v = *(const float4*)(g_xw1 + (long)i * 4);
    float4 b = *(const float4*)(b1 + c4 * 4);
    v.x = v.x * sl + b.x; v.y = v.y * sl + b.y;
    v.z = v.z * sl + b.z; v.w = v.w * sl + b.w;
    *(float4*)(g_out1 + (long)i * 4) = v;
}

// ---------------- layer-1 edge scatter: 16 float4 chunks per edge ----------
__global__ void k_scatter1() {
    long idx = (long)blockIdx.x * blockDim.x + threadIdx.x;
    const long TOT = (long)E_EDGES * 16;
    if (idx >= TOT) return;
    int e = (int)(idx >> 4);
    int c = (int)(idx & 15);
    int s = g_src[e];
    int d = g_dst[e];
    float nrm = g_norm[e];
    float4 v = *(const float4*)(g_xw1 + (long)s * C1 + c * 4);
    float* p = g_out1 + (long)d * C1 + c * 4;
    atomicAdd(p + 0, v.x * nrm);
    atomicAdd(p + 1, v.y * nrm);
    atomicAdd(p + 2, v.z * nrm);
    atomicAdd(p + 3, v.w * nrm);
}

// ---------------- GEMM2: xw2 = relu(out1) @ W2 ([N,64]x[64,40]) ------------
__global__ void k_gemm2(const float* __restrict__ W2) {
    __shared__ float xs[64][68];
    __shared__ float ws[64 * 40];
    int t = threadIdx.x;
    int rb = blockIdx.x * 64;
    int r = t >> 2, q = t & 3;

    for (int i = t; i < 64 * 40; i += 256) ws[i] = W2[i];
#pragma unroll
    for (int it = 0; it < 4; it++) {
        int i = t + 256 * it;
        int rr = i >> 4, cc = (i & 15) << 2;
        int row = rb + rr;
        float4 v = make_float4(0.f, 0.f, 0.f, 0.f);
        if (row < N_NODES)
            v = *(const float4*)(g_out1 + (long)row * C1 + cc);
        v.x = fmaxf(v.x, 0.f); v.y = fmaxf(v.y, 0.f);
        v.z = fmaxf(v.z, 0.f); v.w = fmaxf(v.w, 0.f);
        *(float4*)(&xs[rr][cc]) = v;
    }
    __syncthreads();

    float acc[10];
#pragma unroll
    for (int j = 0; j < 10; j++) acc[j] = 0.0f;
#pragma unroll
    for (int k = 0; k < 64; k++) {
        float xv = xs[r][k];
#pragma unroll
        for (int j = 0; j < 10; j++)
            acc[j] += xv * ws[k * 40 + q * 10 + j];
    }
    int row = rb + r;
    if (row < N_NODES) {
#pragma unroll
        for (int j = 0; j < 10; j++)
            g_xw2[(long)row * C2 + q * 10 + j] = acc[j];
    }
}

// ---------------- init out2 = b2 + xw2 * dinv^2 ----------------------------
__global__ void k_init2(const float* __restrict__ b2) {
    int i = blockIdx.x * blockDim.x + threadIdx.x;   // float4 index
    const int NV = N_NODES * (C2 / 4);
    if (i >= NV) return;
    int row = i / 10;
    int c4 = i - row * 10;
    float dv = g_dinv[row];
    float sl = dv * dv;
    float4 v = *(const float4*)(g_xw2 + (long)i * 4);
    float4 b = *(const float4*)(b2 + c4 * 4);
    v.x = v.x * sl + b.x; v.y = v.y * sl + b.y;
    v.z = v.z * sl + b.z; v.w = v.w * sl + b.w;
    *(float4*)(g_out2 + (long)i * 4) = v;
}

// ---------------- layer-2 edge scatter: 10 float4 chunks per edge ----------
__global__ void k_scatter2() {
    long idx = (long)blockIdx.x * blockDim.x + threadIdx.x;
    const long TOT = (long)E_EDGES * 10;
    if (idx >= TOT) return;
    int e = (int)(idx / 10);
    int c = (int)(idx - (long)e * 10);
    int s = g_src[e];
    int d = g_dst[e];
    float nrm = g_norm[e];
    float4 v = *(const float4*)(g_xw2 + (long)s * C2 + c * 4);
    float* p = g_out2 + (long)d * C2 + c * 4;
    atomicAdd(p + 0, v.x * nrm);
    atomicAdd(p + 1, v.y * nrm);
    atomicAdd(p + 2, v.z * nrm);
    atomicAdd(p + 3, v.w * nrm);
}

// ---------------- log_softmax over 40 classes, warp per row ----------------
__global__ void k_logsoftmax(float* __restrict__ out) {
    int gt = blockIdx.x * blockDim.x + threadIdx.x;
    int w = gt >> 5;
    int lane = gt & 31;
    if (w >= N_NODES) return;
    const float* rp = g_out2 + (long)w * C2;
    float v0 = rp[lane];
    float v1 = (lane < 8) ? rp[32 + lane] : -INFINITY;
    float m = fmaxf(v0, v1);
#pragma unroll
    for (int off = 16; off > 0; off >>= 1)
        m = fmaxf(m, __shfl_xor_sync(0xFFFFFFFFu, m, off));
    float s = expf(v0 - m) + ((lane < 8) ? expf(v1 - m) : 0.0f);
#pragma unroll
    for (int off = 16; off > 0; off >>= 1)
        s += __shfl_xor_sync(0xFFFFFFFFu, s, off);
    float lse = m + logf(s);
    out[(long)w * C2 + lane] = v0 - lse;
    if (lane < 8) out[(long)w * C2 + 32 + lane] = v1 - lse;
}

// ---------------- launch ----------------------------------------------------
extern "C" void kernel_launch(void* const* d_in, const int* in_sizes, int n_in,
                              void* d_out, int out_size) {
    const float* x   = (const float*)d_in[0];
    const int*   ei  = (const int*)d_in[1];
    const float* W1  = (const float*)d_in[2];
    const float* b1  = (const float*)d_in[3];
    const float* W2  = (const float*)d_in[4];
    const float* b2  = (const float*)d_in[5];
    float* out = (float*)d_out;

    const int TB = 256;

    k_detect<<<1, 32>>>(ei);
    k_deg_init<<<(N_NODES + TB - 1) / TB, TB>>>();
    k_deg_count<<<(E_EDGES + TB - 1) / TB, TB>>>(ei);
    k_dinv<<<(N_NODES + TB - 1) / TB, TB>>>();
    k_edge_prep<<<(E_EDGES + TB - 1) / TB, TB>>>(ei);

    k_gemm1<<<(N_NODES + 63) / 64, 256>>>(x, W1);
    k_init1<<<(N_NODES * (C1 / 4) + TB - 1) / TB, TB>>>(b1);
    {
        long tot = (long)E_EDGES * 16;
        k_scatter1<<<(unsigned)((tot + TB - 1) / TB), TB>>>();
    }

    k_gemm2<<<(N_NODES + 63) / 64, 256>>>(W2);
    k_init2<<<(N_NODES * (C2 / 4) + TB - 1) / TB, TB>>>(b2);
    {
        long tot = (long)E_EDGES * 10;
        k_scatter2<<<(unsigned)((tot + TB - 1) / TB), TB>>>();
    }

    k_logsoftmax<<<(N_NODES * 32 + TB - 1) / TB, TB>>>(out);
}

// round 5
// speedup vs baseline: 1.7580x; 1.7580x over previous
#include <cuda_runtime.h>
#include <stdint.h>
#include <math.h>

#define N_NODES 100000
#define E_EDGES 3200000
#define C_IN 256
#define C1 64
#define C2 40
#define SCAN_B 1024
#define NBLK ((N_NODES + SCAN_B - 1) / SCAN_B)   // 98

// ---------------- scratch (device globals; allocation-free) ----------------
__device__ __align__(16) float g_dinv[N_NODES];
__device__ __align__(16) int   g_degi[N_NODES];    // in-degree (edges only)
__device__ __align__(16) int   g_row[N_NODES];     // CSR exclusive row start
__device__ __align__(16) int   g_rowtmp[N_NODES];  // inclusive block scans
__device__ __align__(16) int   g_cur[N_NODES];     // fill cursors
__device__ __align__(16) int   g_bsum[NBLK];
__device__ __align__(16) int   g_boff[NBLK];
__device__ __align__(16) int   g_csrc[E_EDGES];    // CSR src ids (by dst)
__device__ __align__(16) float g_cnorm[E_EDGES];   // CSR edge norms
__device__ __align__(16) float g_xw1[N_NODES * C1];   // x @ W1
__device__ __align__(16) float g_out1[N_NODES * C1];  // aggregated layer-1 (pre-relu)
__device__ __align__(16) float g_xw2[N_NODES * C2];   // relu(out1) @ W2
__device__ int g_is64;

// ---------------- dtype detection (int32 vs int64 edge buffer) -------------
__global__ void k_detect(const int* __restrict__ ei32) {
    if (threadIdx.x == 0) {
        int all0 = 1;
        for (int k = 0; k < 64; k++)
            if (ei32[2 * k + 1] != 0) { all0 = 0; break; }
        g_is64 = all0;
    }
}

__device__ __forceinline__ int load_src(const int* ei32, int e) {
    return g_is64 ? ei32[2 * e] : ei32[e];
}
__device__ __forceinline__ int load_dst(const int* ei32, int e) {
    return g_is64 ? ei32[2 * (E_EDGES + e)] : ei32[E_EDGES + e];
}

// ---------------- CSR build ----------------
__global__ void k_zero() {
    int i = blockIdx.x * blockDim.x + threadIdx.x;
    if (i < N_NODES) { g_degi[i] = 0; g_cur[i] = 0; }
}

__global__ void k_deg_count(const int* __restrict__ ei32) {
    int e = blockIdx.x * blockDim.x + threadIdx.x;
    if (e >= E_EDGES) return;
    atomicAdd(&g_degi[load_dst(ei32, e)], 1);
}

__global__ void k_dinv() {
    int i = blockIdx.x * blockDim.x + threadIdx.x;
    if (i < N_NODES) g_dinv[i] = rsqrtf((float)(g_degi[i] + 1));  // +1 self loop
}

__global__ void k_scan1() {
    __shared__ int sh[SCAN_B];
    int i = blockIdx.x * SCAN_B + threadIdx.x;
    int v = (i < N_NODES) ? g_degi[i] : 0;
    sh[threadIdx.x] = v;
    __syncthreads();
    for (int off = 1; off < SCAN_B; off <<= 1) {
        int t = (threadIdx.x >= off) ? sh[threadIdx.x - off] : 0;
        __syncthreads();
        sh[threadIdx.x] += t;
        __syncthreads();
    }
    if (i < N_NODES) g_rowtmp[i] = sh[threadIdx.x];           // inclusive
    if (threadIdx.x == SCAN_B - 1) g_bsum[blockIdx.x] = sh[SCAN_B - 1];
}

__global__ void k_scan2() {   // single block of 128 threads over NBLK sums
    __shared__ int sh[128];
    int v = (threadIdx.x < NBLK) ? g_bsum[threadIdx.x] : 0;
    sh[threadIdx.x] = v;
    __syncthreads();
    for (int off = 1; off < 128; off <<= 1) {
        int t = (threadIdx.x >= off) ? sh[threadIdx.x - off] : 0;
        __syncthreads();
        sh[threadIdx.x] += t;
        __syncthreads();
    }
    if (threadIdx.x < NBLK) g_boff[threadIdx.x] = sh[threadIdx.x] - v;  // exclusive
}

__global__ void k_scan3() {
    int i = blockIdx.x * blockDim.x + threadIdx.x;
    if (i >= N_NODES) return;
    g_row[i] = g_rowtmp[i] - g_degi[i] + g_boff[i >> 10];     // exclusive start
}

__global__ void k_fill(const int* __restrict__ ei32) {
    int e = blockIdx.x * blockDim.x + threadIdx.x;
    if (e >= E_EDGES) return;
    int s = load_src(ei32, e);
    int d = load_dst(ei32, e);
    int pos = g_row[d] + atomicAdd(&g_cur[d], 1);
    g_csrc[pos] = s;
    g_cnorm[pos] = g_dinv[s] * g_dinv[d];
}

// ---------------- GEMM1: xw1 = x @ W1  ([N,256]x[256,64]) ----------------
__global__ void k_gemm1(const float* __restrict__ x, const float* __restrict__ W1) {
    __shared__ float xs[64][68];
    __shared__ float ws[64][64];
    int t = threadIdx.x;
    int rb = blockIdx.x * 64;
    int r = t >> 2, q = t & 3;

    float acc[16];
#pragma unroll
    for (int j = 0; j < 16; j++) acc[j] = 0.0f;

    for (int kc = 0; kc < C_IN; kc += 64) {
#pragma unroll
        for (int it = 0; it < 4; it++) {
            int i = t + 256 * it;
            int rr = i >> 4, cc = (i & 15) << 2;
            int row = rb + rr;
            float4 v = make_float4(0.f, 0.f, 0.f, 0.f);
            if (row < N_NODES)
                v = *(const float4*)(x + (long)row * C_IN + kc + cc);
            *(float4*)(&xs[rr][cc]) = v;
        }
#pragma unroll
        for (int it = 0; it < 4; it++) {
            int i = t + 256 * it;
            int kk = i >> 4, cc = (i & 15) << 2;
            *(float4*)(&ws[kk][cc]) = *(const float4*)(W1 + (kc + kk) * C1 + cc);
        }
        __syncthreads();

#pragma unroll
        for (int k = 0; k < 64; k++) {
            float xv = xs[r][k];
#pragma unroll
            for (int j4 = 0; j4 < 4; j4++) {
                float4 w4 = *(float4*)(&ws[k][q * 16 + j4 * 4]);
                acc[j4 * 4 + 0] += xv * w4.x;
                acc[j4 * 4 + 1] += xv * w4.y;
                acc[j4 * 4 + 2] += xv * w4.z;
                acc[j4 * 4 + 3] += xv * w4.w;
            }
        }
        __syncthreads();
    }

    int row = rb + r;
    if (row < N_NODES) {
#pragma unroll
        for (int j4 = 0; j4 < 4; j4++) {
            float4 o;
            o.x = acc[j4 * 4 + 0]; o.y = acc[j4 * 4 + 1];
            o.z = acc[j4 * 4 + 2]; o.w = acc[j4 * 4 + 3];
            *(float4*)(g_xw1 + (long)row * C1 + q * 16 + j4 * 4) = o;
        }
    }
}

// ---------------- layer-1 aggregation: warp per node, CSR gather -----------
__global__ void k_agg1(const float* __restrict__ b1) {
    int w = (blockIdx.x * blockDim.x + threadIdx.x) >> 5;
    int lane = threadIdx.x & 31;
    if (w >= N_NODES) return;
    float dv = g_dinv[w];
    float sl = dv * dv;
    const float* xr = g_xw1 + (long)w * C1;
    float a0 = xr[lane]      * sl + b1[lane];
    float a1 = xr[32 + lane] * sl + b1[32 + lane];
    int j = g_row[w];
    int end = j + g_degi[w];

    for (; j + 4 <= end; j += 4) {
        int   s0 = g_csrc[j],     s1 = g_csrc[j + 1];
        int   s2 = g_csrc[j + 2], s3 = g_csrc[j + 3];
        float n0 = g_cnorm[j],     n1 = g_cnorm[j + 1];
        float n2 = g_cnorm[j + 2], n3 = g_cnorm[j + 3];
        const float* p0 = g_xw1 + (long)s0 * C1;
        const float* p1 = g_xw1 + (long)s1 * C1;
        const float* p2 = g_xw1 + (long)s2 * C1;
        const float* p3 = g_xw1 + (long)s3 * C1;
        float v00 = p0[lane], v01 = p0[32 + lane];
        float v10 = p1[lane], v11 = p1[32 + lane];
        float v20 = p2[lane], v21 = p2[32 + lane];
        float v30 = p3[lane], v31 = p3[32 + lane];
        a0 += v00 * n0; a1 += v01 * n0;
        a0 += v10 * n1; a1 += v11 * n1;
        a0 += v20 * n2; a1 += v21 * n2;
        a0 += v30 * n3; a1 += v31 * n3;
    }
    for (; j < end; j++) {
        int s = g_csrc[j];
        float nrm = g_cnorm[j];
        const float* p = g_xw1 + (long)s * C1;
        a0 += p[lane] * nrm;
        a1 += p[32 + lane] * nrm;
    }
    float* o = g_out1 + (long)w * C1;
    o[lane] = a0;
    o[32 + lane] = a1;
}

// ---------------- GEMM2: xw2 = relu(out1) @ W2 ([N,64]x[64,40]) ------------
__global__ void k_gemm2(const float* __restrict__ W2) {
    __shared__ float xs[64][68];
    __shared__ float ws[64 * 40];
    int t = threadIdx.x;
    int rb = blockIdx.x * 64;
    int r = t >> 2, q = t & 3;

    for (int i = t; i < 64 * 40; i += 256) ws[i] = W2[i];
#pragma unroll
    for (int it = 0; it < 4; it++) {
        int i = t + 256 * it;
        int rr = i >> 4, cc = (i & 15) << 2;
        int row = rb + rr;
        float4 v = make_float4(0.f, 0.f, 0.f, 0.f);
        if (row < N_NODES)
            v = *(const float4*)(g_out1 + (long)row * C1 + cc);
        v.x = fmaxf(v.x, 0.f); v.y = fmaxf(v.y, 0.f);
        v.z = fmaxf(v.z, 0.f); v.w = fmaxf(v.w, 0.f);
        *(float4*)(&xs[rr][cc]) = v;
    }
    __syncthreads();

    float acc[10];
#pragma unroll
    for (int j = 0; j < 10; j++) acc[j] = 0.0f;
#pragma unroll
    for (int k = 0; k < 64; k++) {
        float xv = xs[r][k];
#pragma unroll
        for (int j = 0; j < 10; j++)
            acc[j] += xv * ws[k * 40 + q * 10 + j];
    }
    int row = rb + r;
    if (row < N_NODES) {
#pragma unroll
        for (int j = 0; j < 10; j++)
            g_xw2[(long)row * C2 + q * 10 + j] = acc[j];
    }
}

// ---------- layer-2 aggregation + fused log_softmax: warp per node ---------
__global__ void k_agg2_lsm(const float* __restrict__ b2, float* __restrict__ out) {
    int w = (blockIdx.x * blockDim.x + threadIdx.x) >> 5;
    int lane = threadIdx.x & 31;
    if (w >= N_NODES) return;
    bool hi = (lane < 8);
    float dv = g_dinv[w];
    float sl = dv * dv;
    const float* xr = g_xw2 + (long)w * C2;
    float a0 = xr[lane] * sl + b2[lane];
    float a1 = hi ? (xr[32 + lane] * sl + b2[32 + lane]) : 0.0f;
    int j = g_row[w];
    int end = j + g_degi[w];

    for (; j + 4 <= end; j += 4) {
        int   s0 = g_csrc[j],     s1 = g_csrc[j + 1];
        int   s2 = g_csrc[j + 2], s3 = g_csrc[j + 3];
        float n0 = g_cnorm[j],     n1 = g_cnorm[j + 1];
        float n2 = g_cnorm[j + 2], n3 = g_cnorm[j + 3];
        const float* p0 = g_xw2 + (long)s0 * C2;
        const float* p1 = g_xw2 + (long)s1 * C2;
        const float* p2 = g_xw2 + (long)s2 * C2;
        const float* p3 = g_xw2 + (long)s3 * C2;
        a0 += p0[lane] * n0;
        a0 += p1[lane] * n1;
        a0 += p2[lane] * n2;
        a0 += p3[lane] * n3;
        if (hi) {
            a1 += p0[32 + lane] * n0;
            a1 += p1[32 + lane] * n1;
            a1 += p2[32 + lane] * n2;
            a1 += p3[32 + lane] * n3;
        }
    }
    for (; j < end; j++) {
        int s = g_csrc[j];
        float nrm = g_cnorm[j];
        const float* p = g_xw2 + (long)s * C2;
        a0 += p[lane] * nrm;
        if (hi) a1 += p[32 + lane] * nrm;
    }

    // fused log_softmax over the 40 values held in (a0 all lanes, a1 lanes<8)
    float v1 = hi ? a1 : -INFINITY;
    float m = fmaxf(a0, v1);
#pragma unroll
    for (int off = 16; off > 0; off >>= 1)
        m = fmaxf(m, __shfl_xor_sync(0xFFFFFFFFu, m, off));
    float s = expf(a0 - m) + (hi ? expf(a1 - m) : 0.0f);
#pragma unroll
    for (int off = 16; off > 0; off >>= 1)
        s += __shfl_xor_sync(0xFFFFFFFFu, s, off);
    float lse = m + logf(s);
    float* o = out + (long)w * C2;
    o[lane] = a0 - lse;
    if (hi) o[32 + lane] = a1 - lse;
}

// ---------------- launch ----------------------------------------------------
extern "C" void kernel_launch(void* const* d_in, const int* in_sizes, int n_in,
                              void* d_out, int out_size) {
    const float* x   = (const float*)d_in[0];
    const int*   ei  = (const int*)d_in[1];
    const float* W1  = (const float*)d_in[2];
    const float* b1  = (const float*)d_in[3];
    const float* W2  = (const float*)d_in[4];
    const float* b2  = (const float*)d_in[5];
    float* out = (float*)d_out;

    const int TB = 256;

    k_detect<<<1, 32>>>(ei);
    k_zero<<<(N_NODES + TB - 1) / TB, TB>>>();
    k_deg_count<<<(E_EDGES + TB - 1) / TB, TB>>>(ei);
    k_dinv<<<(N_NODES + TB - 1) / TB, TB>>>();
    k_scan1<<<NBLK, SCAN_B>>>();
    k_scan2<<<1, 128>>>();
    k_scan3<<<(N_NODES + TB - 1) / TB, TB>>>();
    k_fill<<<(E_EDGES + TB - 1) / TB, TB>>>(ei);

    k_gemm1<<<(N_NODES + 63) / 64, 256>>>(x, W1);
    k_agg1<<<(N_NODES * 32 + TB - 1) / TB, TB>>>(b1);

    k_gemm2<<<(N_NODES + 63) / 64, 256>>>(W2);
    k_agg2_lsm<<<(N_NODES * 32 + TB - 1) / TB, TB>>>(b2, out);
}

// round 6
// speedup vs baseline: 1.8171x; 1.0336x over previous
#include <cuda_runtime.h>
#include <stdint.h>
#include <math.h>

#define N_NODES 100000
#define E_EDGES 3200000
#define C_IN 256
#define C1 64
#define C2 40
#define SCAN_B 1024
#define NBLK ((N_NODES + SCAN_B - 1) / SCAN_B)   // 98

// ---------------- scratch (device globals; allocation-free) ----------------
__device__ __align__(16) float g_dinv[N_NODES];
__device__ __align__(16) int   g_degi[N_NODES];    // in-degree (edges only)
__device__ __align__(16) int   g_row[N_NODES];     // CSR exclusive row start
__device__ __align__(16) int   g_rowtmp[N_NODES];  // inclusive block scans
__device__ __align__(16) int   g_cur[N_NODES];     // fill cursors (init = row)
__device__ __align__(16) int   g_bsum[NBLK];
__device__ __align__(16) int   g_boff[NBLK];
__device__ __align__(16) int2  g_edge[E_EDGES];    // CSR: {src, norm bits}
__device__ __align__(16) float g_xw1[N_NODES * C1];   // x @ W1
__device__ __align__(16) float g_out1[N_NODES * C1];  // aggregated layer-1 (pre-relu)
__device__ __align__(16) float g_xw2[N_NODES * C2];   // relu(out1) @ W2
__device__ int g_is64;

// ---------------- zero + dtype detection ------------------------------------
__global__ void k_zero_detect(const int* __restrict__ ei32) {
    int i = blockIdx.x * blockDim.x + threadIdx.x;
    if (i < N_NODES) g_degi[i] = 0;
    if (i == 0) {
        int all0 = 1;
        for (int k = 0; k < 64; k++)
            if (ei32[2 * k + 1] != 0) { all0 = 0; break; }
        g_is64 = all0;
    }
}

__device__ __forceinline__ int load_src(const int* ei32, int e) {
    return g_is64 ? ei32[2 * e] : ei32[e];
}
__device__ __forceinline__ int load_dst(const int* ei32, int e) {
    return g_is64 ? ei32[2 * (E_EDGES + e)] : ei32[E_EDGES + e];
}

// ---------------- CSR build ----------------
__global__ void k_deg_count(const int* __restrict__ ei32) {
    int e = blockIdx.x * blockDim.x + threadIdx.x;
    if (e >= E_EDGES) return;
    atomicAdd(&g_degi[load_dst(ei32, e)], 1);
}

__global__ void k_scan1_dinv() {
    __shared__ int sh[SCAN_B];
    int i = blockIdx.x * SCAN_B + threadIdx.x;
    int v = (i < N_NODES) ? g_degi[i] : 0;
    if (i < N_NODES) g_dinv[i] = rsqrtf((float)(v + 1));     // +1 self loop
    sh[threadIdx.x] = v;
    __syncthreads();
    for (int off = 1; off < SCAN_B; off <<= 1) {
        int t = (threadIdx.x >= off) ? sh[threadIdx.x - off] : 0;
        __syncthreads();
        sh[threadIdx.x] += t;
        __syncthreads();
    }
    if (i < N_NODES) g_rowtmp[i] = sh[threadIdx.x];           // inclusive
    if (threadIdx.x == SCAN_B - 1) g_bsum[blockIdx.x] = sh[SCAN_B - 1];
}

__global__ void k_scan2() {   // single block of 128 threads over NBLK sums
    __shared__ int sh[128];
    int v = (threadIdx.x < NBLK) ? g_bsum[threadIdx.x] : 0;
    sh[threadIdx.x] = v;
    __syncthreads();
    for (int off = 1; off < 128; off <<= 1) {
        int t = (threadIdx.x >= off) ? sh[threadIdx.x - off] : 0;
        __syncthreads();
        sh[threadIdx.x] += t;
        __syncthreads();
    }
    if (threadIdx.x < NBLK) g_boff[threadIdx.x] = sh[threadIdx.x] - v;  // exclusive
}

__global__ void k_scan3() {
    int i = blockIdx.x * blockDim.x + threadIdx.x;
    if (i >= N_NODES) return;
    int r = g_rowtmp[i] - g_degi[i] + g_boff[i >> 10];        // exclusive start
    g_row[i] = r;
    g_cur[i] = r;
}

__global__ void k_fill(const int* __restrict__ ei32) {
    int e = blockIdx.x * blockDim.x + threadIdx.x;
    if (e >= E_EDGES) return;
    int s = load_src(ei32, e);
    int d = load_dst(ei32, e);
    int pos = atomicAdd(&g_cur[d], 1);
    float nrm = g_dinv[s] * g_dinv[d];
    g_edge[pos] = make_int2(s, __float_as_int(nrm));
}

// ---------------- GEMM1: xw1 = x @ W1  ([N,256]x[256,64]) ----------------
__global__ void k_gemm1(const float* __restrict__ x, const float* __restrict__ W1) {
    __shared__ float xs[64][68];
    __shared__ float ws[64][64];
    int t = threadIdx.x;
    int rb = blockIdx.x * 64;
    int r = t >> 2, q = t & 3;

    float acc[16];
#pragma unroll
    for (int j = 0; j < 16; j++) acc[j] = 0.0f;

    for (int kc = 0; kc < C_IN; kc += 64) {
#pragma unroll
        for (int it = 0; it < 4; it++) {
            int i = t + 256 * it;
            int rr = i >> 4, cc = (i & 15) << 2;
            int row = rb + rr;
            float4 v = make_float4(0.f, 0.f, 0.f, 0.f);
            if (row < N_NODES)
                v = *(const float4*)(x + (long)row * C_IN + kc + cc);
            *(float4*)(&xs[rr][cc]) = v;
        }
#pragma unroll
        for (int it = 0; it < 4; it++) {
            int i = t + 256 * it;
            int kk = i >> 4, cc = (i & 15) << 2;
            *(float4*)(&ws[kk][cc]) = *(const float4*)(W1 + (kc + kk) * C1 + cc);
        }
        __syncthreads();

#pragma unroll
        for (int k = 0; k < 64; k++) {
            float xv = xs[r][k];
#pragma unroll
            for (int j4 = 0; j4 < 4; j4++) {
                float4 w4 = *(float4*)(&ws[k][q * 16 + j4 * 4]);
                acc[j4 * 4 + 0] += xv * w4.x;
                acc[j4 * 4 + 1] += xv * w4.y;
                acc[j4 * 4 + 2] += xv * w4.z;
                acc[j4 * 4 + 3] += xv * w4.w;
            }
        }
        __syncthreads();
    }

    int row = rb + r;
    if (row < N_NODES) {
#pragma unroll
        for (int j4 = 0; j4 < 4; j4++) {
            float4 o;
            o.x = acc[j4 * 4 + 0]; o.y = acc[j4 * 4 + 1];
            o.z = acc[j4 * 4 + 2]; o.w = acc[j4 * 4 + 3];
            *(float4*)(g_xw1 + (long)row * C1 + q * 16 + j4 * 4) = o;
        }
    }
}

// ---------------- layer-1 aggregation: warp per node, CSR gather -----------
__global__ void k_agg1(const float* __restrict__ b1) {
    int w = (blockIdx.x * blockDim.x + threadIdx.x) >> 5;
    int lane = threadIdx.x & 31;
    if (w >= N_NODES) return;
    float dv = g_dinv[w];
    float sl = dv * dv;
    const float* xr = g_xw1 + (long)w * C1;
    float a0 = xr[lane]      * sl + b1[lane];
    float a1 = xr[32 + lane] * sl + b1[32 + lane];
    int j = g_row[w];
    int end = j + g_degi[w];

    for (; j + 4 <= end; j += 4) {
        int2 e0 = g_edge[j],     e1 = g_edge[j + 1];
        int2 e2 = g_edge[j + 2], e3 = g_edge[j + 3];
        float n0 = __int_as_float(e0.y), n1 = __int_as_float(e1.y);
        float n2 = __int_as_float(e2.y), n3 = __int_as_float(e3.y);
        const float* p0 = g_xw1 + (long)e0.x * C1;
        const float* p1 = g_xw1 + (long)e1.x * C1;
        const float* p2 = g_xw1 + (long)e2.x * C1;
        const float* p3 = g_xw1 + (long)e3.x * C1;
        float v00 = p0[lane], v01 = p0[32 + lane];
        float v10 = p1[lane], v11 = p1[32 + lane];
        float v20 = p2[lane], v21 = p2[32 + lane];
        float v30 = p3[lane], v31 = p3[32 + lane];
        a0 += v00 * n0; a1 += v01 * n0;
        a0 += v10 * n1; a1 += v11 * n1;
        a0 += v20 * n2; a1 += v21 * n2;
        a0 += v30 * n3; a1 += v31 * n3;
    }
    for (; j < end; j++) {
        int2 e = g_edge[j];
        float nrm = __int_as_float(e.y);
        const float* p = g_xw1 + (long)e.x * C1;
        a0 += p[lane] * nrm;
        a1 += p[32 + lane] * nrm;
    }
    float* o = g_out1 + (long)w * C1;
    o[lane] = a0;
    o[32 + lane] = a1;
}

// ---------------- GEMM2: xw2 = relu(out1) @ W2 ([N,64]x[64,40]) ------------
__global__ void k_gemm2(const float* __restrict__ W2) {
    __shared__ float xs[64][68];
    __shared__ float ws[64 * 40];
    int t = threadIdx.x;
    int rb = blockIdx.x * 64;
    int r = t >> 2, q = t & 3;

    for (int i = t; i < 64 * 40; i += 256) ws[i] = W2[i];
#pragma unroll
    for (int it = 0; it < 4; it++) {
        int i = t + 256 * it;
        int rr = i >> 4, cc = (i & 15) << 2;
        int row = rb + rr;
        float4 v = make_float4(0.f, 0.f, 0.f, 0.f);
        if (row < N_NODES)
            v = *(const float4*)(g_out1 + (long)row * C1 + cc);
        v.x = fmaxf(v.x, 0.f); v.y = fmaxf(v.y, 0.f);
        v.z = fmaxf(v.z, 0.f); v.w = fmaxf(v.w, 0.f);
        *(float4*)(&xs[rr][cc]) = v;
    }
    __syncthreads();

    float acc[10];
#pragma unroll
    for (int j = 0; j < 10; j++) acc[j] = 0.0f;
#pragma unroll
    for (int k = 0; k < 64; k++) {
        float xv = xs[r][k];
#pragma unroll
        for (int j = 0; j < 10; j++)
            acc[j] += xv * ws[k * 40 + q * 10 + j];
    }
    int row = rb + r;
    if (row < N_NODES) {
#pragma unroll
        for (int j = 0; j < 10; j++)
            g_xw2[(long)row * C2 + q * 10 + j] = acc[j];
    }
}

// ---------- layer-2 aggregation + fused log_softmax: warp per node ---------
__global__ void k_agg2_lsm(const float* __restrict__ b2, float* __restrict__ out) {
    int w = (blockIdx.x * blockDim.x + threadIdx.x) >> 5;
    int lane = threadIdx.x & 31;
    if (w >= N_NODES) return;
    bool hi = (lane < 8);
    float dv = g_dinv[w];
    float sl = dv * dv;
    const float* xr = g_xw2 + (long)w * C2;
    float a0 = xr[lane] * sl + b2[lane];
    float a1 = hi ? (xr[32 + lane] * sl + b2[32 + lane]) : 0.0f;
    int j = g_row[w];
    int end = j + g_degi[w];

    for (; j + 4 <= end; j += 4) {
        int2 e0 = g_edge[j],     e1 = g_edge[j + 1];
        int2 e2 = g_edge[j + 2], e3 = g_edge[j + 3];
        float n0 = __int_as_float(e0.y), n1 = __int_as_float(e1.y);
        float n2 = __int_as_float(e2.y), n3 = __int_as_float(e3.y);
        const float* p0 = g_xw2 + (long)e0.x * C2;
        const float* p1 = g_xw2 + (long)e1.x * C2;
        const float* p2 = g_xw2 + (long)e2.x * C2;
        const float* p3 = g_xw2 + (long)e3.x * C2;
        a0 += p0[lane] * n0;
        a0 += p1[lane] * n1;
        a0 += p2[lane] * n2;
        a0 += p3[lane] * n3;
        if (hi) {
            a1 += p0[32 + lane] * n0;
            a1 += p1[32 + lane] * n1;
            a1 += p2[32 + lane] * n2;
            a1 += p3[32 + lane] * n3;
        }
    }
    for (; j < end; j++) {
        int2 e = g_edge[j];
        float nrm = __int_as_float(e.y);
        const float* p = g_xw2 + (long)e.x * C2;
        a0 += p[lane] * nrm;
        if (hi) a1 += p[32 + lane] * nrm;
    }

    // fused log_softmax over the 40 values held in (a0 all lanes, a1 lanes<8)
    float v1 = hi ? a1 : -INFINITY;
    float m = fmaxf(a0, v1);
#pragma unroll
    for (int off = 16; off > 0; off >>= 1)
        m = fmaxf(m, __shfl_xor_sync(0xFFFFFFFFu, m, off));
    float s = expf(a0 - m) + (hi ? expf(a1 - m) : 0.0f);
#pragma unroll
    for (int off = 16; off > 0; off >>= 1)
        s += __shfl_xor_sync(0xFFFFFFFFu, s, off);
    float lse = m + logf(s);
    float* o = out + (long)w * C2;
    o[lane] = a0 - lse;
    if (hi) o[32 + lane] = a1 - lse;
}

// ---------------- launch ----------------------------------------------------
extern "C" void kernel_launch(void* const* d_in, const int* in_sizes, int n_in,
                              void* d_out, int out_size) {
    const float* x   = (const float*)d_in[0];
    const int*   ei  = (const int*)d_in[1];
    const float* W1  = (const float*)d_in[2];
    const float* b1  = (const float*)d_in[3];
    const float* W2  = (const float*)d_in[4];
    const float* b2  = (const float*)d_in[5];
    float* out = (float*)d_out;

    const int TB = 256;

    k_zero_detect<<<(N_NODES + TB - 1) / TB, TB>>>(ei);          // 1
    k_deg_count<<<(E_EDGES + TB - 1) / TB, TB>>>(ei);            // 2
    k_scan1_dinv<<<NBLK, SCAN_B>>>();                            // 3
    k_gemm1<<<(N_NODES + 63) / 64, 256>>>(x, W1);                // 4 (profiled slot)
    k_scan2<<<1, 128>>>();                                       // 5
    k_scan3<<<(N_NODES + TB - 1) / TB, TB>>>();                  // 6
    k_fill<<<(E_EDGES + TB - 1) / TB, TB>>>(ei);                 // 7
    k_agg1<<<(N_NODES * 32 + TB - 1) / TB, TB>>>(b1);            // 8
    k_gemm2<<<(N_NODES + 63) / 64, 256>>>(W2);                   // 9
    k_agg2_lsm<<<(N_NODES * 32 + TB - 1) / TB, TB>>>(b2, out);   // 10
}

// round 7
// speedup vs baseline: 3.3318x; 1.8336x over previous
#include <cuda_runtime.h>
#include <stdint.h>
#include <math.h>

#define N_NODES 100000
#define E_EDGES 3200000
#define C_IN 256
#define C1 64
#define C2 40
#define SCAN_B 1024
#define NBLK ((N_NODES + SCAN_B - 1) / SCAN_B)   // 98

// ---------------- scratch (device globals; allocation-free) ----------------
__device__ __align__(16) float g_dinv[N_NODES];
__device__ __align__(16) int   g_degi[N_NODES];
__device__ __align__(16) int   g_row[N_NODES];
__device__ __align__(16) int   g_rowtmp[N_NODES];
__device__ __align__(16) int   g_cur[N_NODES];
__device__ __align__(16) int   g_bsum[NBLK];
__device__ __align__(16) int   g_boff[NBLK];
__device__ __align__(16) int2  g_edge[E_EDGES];    // CSR: {src, norm bits}
__device__ __align__(16) float g_xw1[(N_NODES + 128) * C1];
__device__ __align__(16) float g_out1[N_NODES * C1];
__device__ __align__(16) float g_xw2[N_NODES * C2];
__device__ int g_is64;

// ---------------- zero + dtype detection ------------------------------------
__global__ void k_zero_detect(const int* __restrict__ ei32) {
    int i = blockIdx.x * blockDim.x + threadIdx.x;
    if (i < N_NODES) g_degi[i] = 0;
    if (i == 0) {
        int all0 = 1;
        for (int k = 0; k < 64; k++)
            if (ei32[2 * k + 1] != 0) { all0 = 0; break; }
        g_is64 = all0;
    }
}

__device__ __forceinline__ int load_src(const int* ei32, int e) {
    return g_is64 ? ei32[2 * e] : ei32[e];
}
__device__ __forceinline__ int load_dst(const int* ei32, int e) {
    return g_is64 ? ei32[2 * (E_EDGES + e)] : ei32[E_EDGES + e];
}

// ---------------- CSR build ----------------
__global__ void k_deg_count(const int* __restrict__ ei32) {
    int e = blockIdx.x * blockDim.x + threadIdx.x;
    if (e >= E_EDGES) return;
    atomicAdd(&g_degi[load_dst(ei32, e)], 1);
}

__global__ void k_scan1_dinv() {
    __shared__ int sh[SCAN_B];
    int i = blockIdx.x * SCAN_B + threadIdx.x;
    int v = (i < N_NODES) ? g_degi[i] : 0;
    if (i < N_NODES) g_dinv[i] = rsqrtf((float)(v + 1));     // +1 self loop
    sh[threadIdx.x] = v;
    __syncthreads();
    for (int off = 1; off < SCAN_B; off <<= 1) {
        int t = (threadIdx.x >= off) ? sh[threadIdx.x - off] : 0;
        __syncthreads();
        sh[threadIdx.x] += t;
        __syncthreads();
    }
    if (i < N_NODES) g_rowtmp[i] = sh[threadIdx.x];
    if (threadIdx.x == SCAN_B - 1) g_bsum[blockIdx.x] = sh[SCAN_B - 1];
}

__global__ void k_scan2() {
    __shared__ int sh[128];
    int v = (threadIdx.x < NBLK) ? g_bsum[threadIdx.x] : 0;
    sh[threadIdx.x] = v;
    __syncthreads();
    for (int off = 1; off < 128; off <<= 1) {
        int t = (threadIdx.x >= off) ? sh[threadIdx.x - off] : 0;
        __syncthreads();
        sh[threadIdx.x] += t;
        __syncthreads();
    }
    if (threadIdx.x < NBLK) g_boff[threadIdx.x] = sh[threadIdx.x] - v;
}

__global__ void k_scan3() {
    int i = blockIdx.x * blockDim.x + threadIdx.x;
    if (i >= N_NODES) return;
    int r = g_rowtmp[i] - g_degi[i] + g_boff[i >> 10];
    g_row[i] = r;
    g_cur[i] = r;
}

__global__ void k_fill(const int* __restrict__ ei32) {
    int e = blockIdx.x * blockDim.x + threadIdx.x;
    if (e >= E_EDGES) return;
    int s = load_src(ei32, e);
    int d = load_dst(ei32, e);
    int pos = atomicAdd(&g_cur[d], 1);
    float nrm = g_dinv[s] * g_dinv[d];
    g_edge[pos] = make_int2(s, __float_as_int(nrm));
}

// ---------------- GEMM1: xw1 = x @ W1, register-tiled 8x4 ------------------
// Block tile 128 rows x 64 cols, 256 threads; thread (tr,tc) = (tid>>4, tid&15)
// computes rows tr*8..tr*8+7, cols tc*4..tc*4+3. K tiled by 32, x stored
// k-major (transposed) in smem.
#define G1_KT 32
#define XS_STRIDE 132   // 132*4 bytes: 16B-aligned rows, conflict-managed

__global__ void k_gemm1(const float* __restrict__ x, const float* __restrict__ W1) {
    __shared__ float xs[G1_KT][XS_STRIDE];   // [k][row]
    __shared__ float ws[G1_KT][64];          // [k][col]
    int tid = threadIdx.x;
    int tr = tid >> 4;         // 0..15
    int tc = tid & 15;         // 0..15
    int rb = blockIdx.x * 128;

    float acc[8][4];
#pragma unroll
    for (int i = 0; i < 8; i++)
#pragma unroll
        for (int j = 0; j < 4; j++) acc[i][j] = 0.0f;

    for (int kc = 0; kc < C_IN; kc += G1_KT) {
        // load x tile: 128 rows x 32 k, transposed into xs[k][row]
#pragma unroll
        for (int it = 0; it < 4; it++) {
            int i = tid + 256 * it;
            int row = i >> 3;
            int k4 = (i & 7) << 2;
            int grow = rb + row;
            float4 v = make_float4(0.f, 0.f, 0.f, 0.f);
            if (grow < N_NODES)
                v = *(const float4*)(x + (long)grow * C_IN + kc + k4);
            xs[k4 + 0][row] = v.x;
            xs[k4 + 1][row] = v.y;
            xs[k4 + 2][row] = v.z;
            xs[k4 + 3][row] = v.w;
        }
        // load W tile: 32 k x 64 cols
#pragma unroll
        for (int it = 0; it < 2; it++) {
            int i = tid + 256 * it;
            int wk = i >> 4;
            int wc = (i & 15) << 2;
            *(float4*)(&ws[wk][wc]) = *(const float4*)(W1 + (kc + wk) * C1 + wc);
        }
        __syncthreads();

#pragma unroll 8
        for (int k = 0; k < G1_KT; k++) {
            float4 xa = *(float4*)(&xs[k][tr * 8]);
            float4 xb = *(float4*)(&xs[k][tr * 8 + 4]);
            float4 wv = *(float4*)(&ws[k][tc * 4]);
            float xr[8] = {xa.x, xa.y, xa.z, xa.w, xb.x, xb.y, xb.z, xb.w};
#pragma unroll
            for (int i = 0; i < 8; i++) {
                acc[i][0] += xr[i] * wv.x;
                acc[i][1] += xr[i] * wv.y;
                acc[i][2] += xr[i] * wv.z;
                acc[i][3] += xr[i] * wv.w;
            }
        }
        __syncthreads();
    }

#pragma unroll
    for (int i = 0; i < 8; i++) {
        int grow = rb + tr * 8 + i;
        if (grow < N_NODES) {
            float4 o;
            o.x = acc[i][0]; o.y = acc[i][1]; o.z = acc[i][2]; o.w = acc[i][3];
            *(float4*)(g_xw1 + (long)grow * C1 + tc * 4) = o;
        }
    }
}

// ---------------- layer-1 aggregation: warp per node, CSR gather -----------
__global__ void k_agg1(const float* __restrict__ b1) {
    int w = (blockIdx.x * blockDim.x + threadIdx.x) >> 5;
    int lane = threadIdx.x & 31;
    if (w >= N_NODES) return;
    float dv = g_dinv[w];
    float sl = dv * dv;
    const float* xr = g_xw1 + (long)w * C1;
    float a0 = xr[lane]      * sl + b1[lane];
    float a1 = xr[32 + lane] * sl + b1[32 + lane];
    int j = g_row[w];
    int end = j + g_degi[w];

    for (; j + 4 <= end; j += 4) {
        int2 e0 = g_edge[j],     e1 = g_edge[j + 1];
        int2 e2 = g_edge[j + 2], e3 = g_edge[j + 3];
        float n0 = __int_as_float(e0.y), n1 = __int_as_float(e1.y);
        float n2 = __int_as_float(e2.y), n3 = __int_as_float(e3.y);
        const float* p0 = g_xw1 + (long)e0.x * C1;
        const float* p1 = g_xw1 + (long)e1.x * C1;
        const float* p2 = g_xw1 + (long)e2.x * C1;
        const float* p3 = g_xw1 + (long)e3.x * C1;
        float v00 = p0[lane], v01 = p0[32 + lane];
        float v10 = p1[lane], v11 = p1[32 + lane];
        float v20 = p2[lane], v21 = p2[32 + lane];
        float v30 = p3[lane], v31 = p3[32 + lane];
        a0 += v00 * n0; a1 += v01 * n0;
        a0 += v10 * n1; a1 += v11 * n1;
        a0 += v20 * n2; a1 += v21 * n2;
        a0 += v30 * n3; a1 += v31 * n3;
    }
    for (; j < end; j++) {
        int2 e = g_edge[j];
        float nrm = __int_as_float(e.y);
        const float* p = g_xw1 + (long)e.x * C1;
        a0 += p[lane] * nrm;
        a1 += p[32 + lane] * nrm;
    }
    float* o = g_out1 + (long)w * C1;
    o[lane] = a0;
    o[32 + lane] = a1;
}

// ---------------- GEMM2: xw2 = relu(out1) @ W2 ([N,64]x[64,40]) ------------
__global__ void k_gemm2(const float* __restrict__ W2) {
    __shared__ float xs[64][68];
    __shared__ float ws[64 * 40];
    int t = threadIdx.x;
    int rb = blockIdx.x * 64;
    int r = t >> 2, q = t & 3;

    for (int i = t; i < 64 * 40; i += 256) ws[i] = W2[i];
#pragma unroll
    for (int it = 0; it < 4; it++) {
        int i = t + 256 * it;
        int rr = i >> 4, cc = (i & 15) << 2;
        int row = rb + rr;
        float4 v = make_float4(0.f, 0.f, 0.f, 0.f);
        if (row < N_NODES)
            v = *(const float4*)(g_out1 + (long)row * C1 + cc);
        v.x = fmaxf(v.x, 0.f); v.y = fmaxf(v.y, 0.f);
        v.z = fmaxf(v.z, 0.f); v.w = fmaxf(v.w, 0.f);
        *(float4*)(&xs[rr][cc]) = v;
    }
    __syncthreads();

    float acc[10];
#pragma unroll
    for (int j = 0; j < 10; j++) acc[j] = 0.0f;
#pragma unroll
    for (int k = 0; k < 64; k++) {
        float xv = xs[r][k];
#pragma unroll
        for (int j = 0; j < 10; j++)
            acc[j] += xv * ws[k * 40 + q * 10 + j];
    }
    int row = rb + r;
    if (row < N_NODES) {
#pragma unroll
        for (int j = 0; j < 10; j++)
            g_xw2[(long)row * C2 + q * 10 + j] = acc[j];
    }
}

// ---------- layer-2 aggregation + fused log_softmax: warp per node ---------
__global__ void k_agg2_lsm(const float* __restrict__ b2, float* __restrict__ out) {
    int w = (blockIdx.x * blockDim.x + threadIdx.x) >> 5;
    int lane = threadIdx.x & 31;
    if (w >= N_NODES) return;
    bool hi = (lane < 8);
    float dv = g_dinv[w];
    float sl = dv * dv;
    const float* xr = g_xw2 + (long)w * C2;
    float a0 = xr[lane] * sl + b2[lane];
    float a1 = hi ? (xr[32 + lane] * sl + b2[32 + lane]) : 0.0f;
    int j = g_row[w];
    int end = j + g_degi[w];

    for (; j + 4 <= end; j += 4) {
        int2 e0 = g_edge[j],     e1 = g_edge[j + 1];
        int2 e2 = g_edge[j + 2], e3 = g_edge[j + 3];
        float n0 = __int_as_float(e0.y), n1 = __int_as_float(e1.y);
        float n2 = __int_as_float(e2.y), n3 = __int_as_float(e3.y);
        const float* p0 = g_xw2 + (long)e0.x * C2;
        const float* p1 = g_xw2 + (long)e1.x * C2;
        const float* p2 = g_xw2 + (long)e2.x * C2;
        const float* p3 = g_xw2 + (long)e3.x * C2;
        a0 += p0[lane] * n0;
        a0 += p1[lane] * n1;
        a0 += p2[lane] * n2;
        a0 += p3[lane] * n3;
        if (hi) {
            a1 += p0[32 + lane] * n0;
            a1 += p1[32 + lane] * n1;
            a1 += p2[32 + lane] * n2;
            a1 += p3[32 + lane] * n3;
        }
    }
    for (; j < end; j++) {
        int2 e = g_edge[j];
        float nrm = __int_as_float(e.y);
        const float* p = g_xw2 + (long)e.x * C2;
        a0 += p[lane] * nrm;
        if (hi) a1 += p[32 + lane] * nrm;
    }

    float v1 = hi ? a1 : -INFINITY;
    float m = fmaxf(a0, v1);
#pragma unroll
    for (int off = 16; off > 0; off >>= 1)
        m = fmaxf(m, __shfl_xor_sync(0xFFFFFFFFu, m, off));
    float s = expf(a0 - m) + (hi ? expf(a1 - m) : 0.0f);
#pragma unroll
    for (int off = 16; off > 0; off >>= 1)
        s += __shfl_xor_sync(0xFFFFFFFFu, s, off);
    float lse = m + logf(s);
    float* o = out + (long)w * C2;
    o[lane] = a0 - lse;
    if (hi) o[32 + lane] = a1 - lse;
}

// ---------------- launch ----------------------------------------------------
extern "C" void kernel_launch(void* const* d_in, const int* in_sizes, int n_in,
                              void* d_out, int out_size) {
    const float* x   = (const float*)d_in[0];
    const int*   ei  = (const int*)d_in[1];
    const float* W1  = (const float*)d_in[2];
    const float* b1  = (const float*)d_in[3];
    const float* W2  = (const float*)d_in[4];
    const float* b2  = (const float*)d_in[5];
    float* out = (float*)d_out;

    const int TB = 256;

    k_zero_detect<<<(N_NODES + TB - 1) / TB, TB>>>(ei);          // 1
    k_deg_count<<<(E_EDGES + TB - 1) / TB, TB>>>(ei);            // 2
    k_scan1_dinv<<<NBLK, SCAN_B>>>();                            // 3
    k_gemm1<<<(N_NODES + 127) / 128, 256>>>(x, W1);              // 4 (profiled slot)
    k_scan2<<<1, 128>>>();                                       // 5
    k_scan3<<<(N_NODES + TB - 1) / TB, TB>>>();                  // 6
    k_fill<<<(E_EDGES + TB - 1) / TB, TB>>>(ei);                 // 7
    k_agg1<<<(N_NODES * 32 + TB - 1) / TB, TB>>>(b1);            // 8
    k_gemm2<<<(N_NODES + 63) / 64, 256>>>(W2);                   // 9
    k_agg2_lsm<<<(N_NODES * 32 + TB - 1) / TB, TB>>>(b2, out);   // 10
}

// round 8
// speedup vs baseline: 3.5939x; 1.0787x over previous
#include <cuda_runtime.h>
#include <stdint.h>
#include <math.h>

#define N_NODES 100000
#define E_EDGES 3200000
#define C_IN 256
#define C1 64
#define C2 40
#define SCAN_B 1024
#define NBLK ((N_NODES + SCAN_B - 1) / SCAN_B)   // 98

// ---------------- scratch (device globals; allocation-free) ----------------
__device__ __align__(16) float g_dinv[N_NODES];
__device__ __align__(16) int   g_degi[N_NODES];
__device__ __align__(16) int   g_row[N_NODES];
__device__ __align__(16) int   g_rowtmp[N_NODES];
__device__ __align__(16) int   g_cur[N_NODES];
__device__ __align__(16) int   g_bsum[NBLK];
__device__ __align__(16) int   g_boff[NBLK];
__device__ __align__(16) int2  g_edge[E_EDGES];    // CSR: {src, norm bits}
__device__ __align__(16) float g_xw1[(N_NODES + 128) * C1];
__device__ __align__(16) float g_out1[N_NODES * C1];
__device__ __align__(16) float g_xw2[N_NODES * C2];
__device__ int g_is64;

// ---------------- zero + dtype detection ------------------------------------
__global__ void k_zero_detect(const int* __restrict__ ei32) {
    int i = blockIdx.x * blockDim.x + threadIdx.x;
    if (i < N_NODES) g_degi[i] = 0;
    if (i == 0) {
        int all0 = 1;
        for (int k = 0; k < 64; k++)
            if (ei32[2 * k + 1] != 0) { all0 = 0; break; }
        g_is64 = all0;
    }
}

__device__ __forceinline__ int load_src(const int* ei32, int e) {
    return g_is64 ? ei32[2 * e] : ei32[e];
}
__device__ __forceinline__ int load_dst(const int* ei32, int e) {
    return g_is64 ? ei32[2 * (E_EDGES + e)] : ei32[E_EDGES + e];
}

// ---------------- CSR build ----------------
__global__ void k_deg_count(const int* __restrict__ ei32) {
    int e = blockIdx.x * blockDim.x + threadIdx.x;
    if (e >= E_EDGES) return;
    atomicAdd(&g_degi[load_dst(ei32, e)], 1);
}

__global__ void k_scan1_dinv() {
    __shared__ int sh[SCAN_B];
    int i = blockIdx.x * SCAN_B + threadIdx.x;
    int v = (i < N_NODES) ? g_degi[i] : 0;
    if (i < N_NODES) g_dinv[i] = rsqrtf((float)(v + 1));     // +1 self loop
    sh[threadIdx.x] = v;
    __syncthreads();
    for (int off = 1; off < SCAN_B; off <<= 1) {
        int t = (threadIdx.x >= off) ? sh[threadIdx.x - off] : 0;
        __syncthreads();
        sh[threadIdx.x] += t;
        __syncthreads();
    }
    if (i < N_NODES) g_rowtmp[i] = sh[threadIdx.x];
    if (threadIdx.x == SCAN_B - 1) g_bsum[blockIdx.x] = sh[SCAN_B - 1];
}

__global__ void k_scan2() {
    __shared__ int sh[128];
    int v = (threadIdx.x < NBLK) ? g_bsum[threadIdx.x] : 0;
    sh[threadIdx.x] = v;
    __syncthreads();
    for (int off = 1; off < 128; off <<= 1) {
        int t = (threadIdx.x >= off) ? sh[threadIdx.x - off] : 0;
        __syncthreads();
        sh[threadIdx.x] += t;
        __syncthreads();
    }
    if (threadIdx.x < NBLK) g_boff[threadIdx.x] = sh[threadIdx.x] - v;
}

__global__ void k_scan3() {
    int i = blockIdx.x * blockDim.x + threadIdx.x;
    if (i >= N_NODES) return;
    int r = g_rowtmp[i] - g_degi[i] + g_boff[i >> 10];
    g_row[i] = r;
    g_cur[i] = r;
}

__global__ void k_fill(const int* __restrict__ ei32) {
    int e = blockIdx.x * blockDim.x + threadIdx.x;
    if (e >= E_EDGES) return;
    int s = load_src(ei32, e);
    int d = load_dst(ei32, e);
    int pos = atomicAdd(&g_cur[d], 1);
    float nrm = g_dinv[s] * g_dinv[d];
    g_edge[pos] = make_int2(s, __float_as_int(nrm));
}

// ---------------- GEMM1: xw1 = x @ W1, register-tiled 8x4 ------------------
#define G1_KT 32
#define XS_STRIDE 132

__global__ void k_gemm1(const float* __restrict__ x, const float* __restrict__ W1) {
    __shared__ float xs[G1_KT][XS_STRIDE];   // [k][row]
    __shared__ float ws[G1_KT][64];          // [k][col]
    int tid = threadIdx.x;
    int tr = tid >> 4;         // 0..15
    int tc = tid & 15;         // 0..15
    int rb = blockIdx.x * 128;

    float acc[8][4];
#pragma unroll
    for (int i = 0; i < 8; i++)
#pragma unroll
        for (int j = 0; j < 4; j++) acc[i][j] = 0.0f;

    for (int kc = 0; kc < C_IN; kc += G1_KT) {
#pragma unroll
        for (int it = 0; it < 4; it++) {
            int i = tid + 256 * it;
            int row = i >> 3;
            int k4 = (i & 7) << 2;
            int grow = rb + row;
            float4 v = make_float4(0.f, 0.f, 0.f, 0.f);
            if (grow < N_NODES)
                v = *(const float4*)(x + (long)grow * C_IN + kc + k4);
            xs[k4 + 0][row] = v.x;
            xs[k4 + 1][row] = v.y;
            xs[k4 + 2][row] = v.z;
            xs[k4 + 3][row] = v.w;
        }
#pragma unroll
        for (int it = 0; it < 2; it++) {
            int i = tid + 256 * it;
            int wk = i >> 4;
            int wc = (i & 15) << 2;
            *(float4*)(&ws[wk][wc]) = *(const float4*)(W1 + (kc + wk) * C1 + wc);
        }
        __syncthreads();

#pragma unroll 8
        for (int k = 0; k < G1_KT; k++) {
            float4 xa = *(float4*)(&xs[k][tr * 8]);
            float4 xb = *(float4*)(&xs[k][tr * 8 + 4]);
            float4 wv = *(float4*)(&ws[k][tc * 4]);
            float xr[8] = {xa.x, xa.y, xa.z, xa.w, xb.x, xb.y, xb.z, xb.w};
#pragma unroll
            for (int i = 0; i < 8; i++) {
                acc[i][0] += xr[i] * wv.x;
                acc[i][1] += xr[i] * wv.y;
                acc[i][2] += xr[i] * wv.z;
                acc[i][3] += xr[i] * wv.w;
            }
        }
        __syncthreads();
    }

#pragma unroll
    for (int i = 0; i < 8; i++) {
        int grow = rb + tr * 8 + i;
        if (grow < N_NODES) {
            float4 o;
            o.x = acc[i][0]; o.y = acc[i][1]; o.z = acc[i][2]; o.w = acc[i][3];
            *(float4*)(g_xw1 + (long)grow * C1 + tc * 4) = o;
        }
    }
}

// ---------------- layer-1 aggregation: warp per node, CSR gather -----------
__global__ void k_agg1(const float* __restrict__ b1) {
    int w = (blockIdx.x * blockDim.x + threadIdx.x) >> 5;
    int lane = threadIdx.x & 31;
    if (w >= N_NODES) return;
    float dv = g_dinv[w];
    float sl = dv * dv;
    const float* xr = g_xw1 + (long)w * C1;
    float a0 = xr[lane]      * sl + b1[lane];
    float a1 = xr[32 + lane] * sl + b1[32 + lane];
    int j = g_row[w];
    int end = j + g_degi[w];

    for (; j + 4 <= end; j += 4) {
        int2 e0 = g_edge[j],     e1 = g_edge[j + 1];
        int2 e2 = g_edge[j + 2], e3 = g_edge[j + 3];
        float n0 = __int_as_float(e0.y), n1 = __int_as_float(e1.y);
        float n2 = __int_as_float(e2.y), n3 = __int_as_float(e3.y);
        const float* p0 = g_xw1 + (long)e0.x * C1;
        const float* p1 = g_xw1 + (long)e1.x * C1;
        const float* p2 = g_xw1 + (long)e2.x * C1;
        const float* p3 = g_xw1 + (long)e3.x * C1;
        float v00 = p0[lane], v01 = p0[32 + lane];
        float v10 = p1[lane], v11 = p1[32 + lane];
        float v20 = p2[lane], v21 = p2[32 + lane];
        float v30 = p3[lane], v31 = p3[32 + lane];
        a0 += v00 * n0; a1 += v01 * n0;
        a0 += v10 * n1; a1 += v11 * n1;
        a0 += v20 * n2; a1 += v21 * n2;
        a0 += v30 * n3; a1 += v31 * n3;
    }
    for (; j < end; j++) {
        int2 e = g_edge[j];
        float nrm = __int_as_float(e.y);
        const float* p = g_xw1 + (long)e.x * C1;
        a0 += p[lane] * nrm;
        a1 += p[32 + lane] * nrm;
    }
    float* o = g_out1 + (long)w * C1;
    o[lane] = a0;
    o[32 + lane] = a1;
}

// ---------------- GEMM2: xw2 = relu(out1) @ W2 ([N,64]x[64,40]) ------------
__global__ void k_gemm2(const float* __restrict__ W2) {
    __shared__ float xs[64][68];
    __shared__ float ws[64 * 40];
    int t = threadIdx.x;
    int rb = blockIdx.x * 64;
    int r = t >> 2, q = t & 3;

    for (int i = t; i < 64 * 40; i += 256) ws[i] = W2[i];
#pragma unroll
    for (int it = 0; it < 4; it++) {
        int i = t + 256 * it;
        int rr = i >> 4, cc = (i & 15) << 2;
        int row = rb + rr;
        float4 v = make_float4(0.f, 0.f, 0.f, 0.f);
        if (row < N_NODES)
            v = *(const float4*)(g_out1 + (long)row * C1 + cc);
        v.x = fmaxf(v.x, 0.f); v.y = fmaxf(v.y, 0.f);
        v.z = fmaxf(v.z, 0.f); v.w = fmaxf(v.w, 0.f);
        *(float4*)(&xs[rr][cc]) = v;
    }
    __syncthreads();

    float acc[10];
#pragma unroll
    for (int j = 0; j < 10; j++) acc[j] = 0.0f;
#pragma unroll
    for (int k = 0; k < 64; k++) {
        float xv = xs[r][k];
#pragma unroll
        for (int j = 0; j < 10; j++)
            acc[j] += xv * ws[k * 40 + q * 10 + j];
    }
    int row = rb + r;
    if (row < N_NODES) {
#pragma unroll
        for (int j = 0; j < 10; j++)
            g_xw2[(long)row * C2 + q * 10 + j] = acc[j];
    }
}

// ---------- layer-2 aggregation + fused log_softmax: warp per node ---------
__global__ void k_agg2_lsm(const float* __restrict__ b2, float* __restrict__ out) {
    int w = (blockIdx.x * blockDim.x + threadIdx.x) >> 5;
    int lane = threadIdx.x & 31;
    if (w >= N_NODES) return;
    bool hi = (lane < 8);
    float dv = g_dinv[w];
    float sl = dv * dv;
    const float* xr = g_xw2 + (long)w * C2;
    float a0 = xr[lane] * sl + b2[lane];
    float a1 = hi ? (xr[32 + lane] * sl + b2[32 + lane]) : 0.0f;
    int j = g_row[w];
    int end = j + g_degi[w];

    for (; j + 4 <= end; j += 4) {
        int2 e0 = g_edge[j],     e1 = g_edge[j + 1];
        int2 e2 = g_edge[j + 2], e3 = g_edge[j + 3];
        float n0 = __int_as_float(e0.y), n1 = __int_as_float(e1.y);
        float n2 = __int_as_float(e2.y), n3 = __int_as_float(e3.y);
        const float* p0 = g_xw2 + (long)e0.x * C2;
        const float* p1 = g_xw2 + (long)e1.x * C2;
        const float* p2 = g_xw2 + (long)e2.x * C2;
        const float* p3 = g_xw2 + (long)e3.x * C2;
        a0 += p0[lane] * n0;
        a0 += p1[lane] * n1;
        a0 += p2[lane] * n2;
        a0 += p3[lane] * n3;
        if (hi) {
            a1 += p0[32 + lane] * n0;
            a1 += p1[32 + lane] * n1;
            a1 += p2[32 + lane] * n2;
            a1 += p3[32 + lane] * n3;
        }
    }
    for (; j < end; j++) {
        int2 e = g_edge[j];
        float nrm = __int_as_float(e.y);
        const float* p = g_xw2 + (long)e.x * C2;
        a0 += p[lane] * nrm;
        if (hi) a1 += p[32 + lane] * nrm;
    }

    float v1 = hi ? a1 : -INFINITY;
    float m = fmaxf(a0, v1);
#pragma unroll
    for (int off = 16; off > 0; off >>= 1)
        m = fmaxf(m, __shfl_xor_sync(0xFFFFFFFFu, m, off));
    float s = expf(a0 - m) + (hi ? expf(a1 - m) : 0.0f);
#pragma unroll
    for (int off = 16; off > 0; off >>= 1)
        s += __shfl_xor_sync(0xFFFFFFFFu, s, off);
    float lse = m + logf(s);
    float* o = out + (long)w * C2;
    o[lane] = a0 - lse;
    if (hi) o[32 + lane] = a1 - lse;
}

// ---------------- launch: fork CSR build alongside GEMM1 --------------------
extern "C" void kernel_launch(void* const* d_in, const int* in_sizes, int n_in,
                              void* d_out, int out_size) {
    const float* x   = (const float*)d_in[0];
    const int*   ei  = (const int*)d_in[1];
    const float* W1  = (const float*)d_in[2];
    const float* b1  = (const float*)d_in[3];
    const float* W2  = (const float*)d_in[4];
    const float* b2  = (const float*)d_in[5];
    float* out = (float*)d_out;

    const int TB = 256;

    // persistent side stream + events (host-side handles only; no device mem)
    static cudaStream_t s_csr = nullptr;
    static cudaEvent_t ev_fork = nullptr, ev_join = nullptr;
    if (s_csr == nullptr) {
        cudaStreamCreateWithFlags(&s_csr, cudaStreamNonBlocking);
        cudaEventCreateWithFlags(&ev_fork, cudaEventDisableTiming);
        cudaEventCreateWithFlags(&ev_join, cudaEventDisableTiming);
    }

    // fork: CSR build branch on s_csr, gemm1 on the origin stream
    cudaEventRecord(ev_fork, 0);
    cudaStreamWaitEvent(s_csr, ev_fork, 0);

    k_zero_detect<<<(N_NODES + TB - 1) / TB, TB, 0, s_csr>>>(ei);
    k_deg_count<<<(E_EDGES + TB - 1) / TB, TB, 0, s_csr>>>(ei);
    k_scan1_dinv<<<NBLK, SCAN_B, 0, s_csr>>>();
    k_scan2<<<1, 128, 0, s_csr>>>();
    k_scan3<<<(N_NODES + TB - 1) / TB, TB, 0, s_csr>>>();
    k_fill<<<(E_EDGES + TB - 1) / TB, TB, 0, s_csr>>>(ei);
    cudaEventRecord(ev_join, s_csr);

    k_gemm1<<<(N_NODES + 127) / 128, 256>>>(x, W1);

    // join: aggregation needs both branches
    cudaStreamWaitEvent(0, ev_join, 0);

    k_agg1<<<(N_NODES * 32 + TB - 1) / TB, TB>>>(b1);
    k_gemm2<<<(N_NODES + 63) / 64, 256>>>(W2);
    k_agg2_lsm<<<(N_NODES * 32 + TB - 1) / TB, TB>>>(b2, out);
}

// round 9
// speedup vs baseline: 3.9718x; 1.1051x over previous
#include <cuda_runtime.h>
#include <stdint.h>
#include <math.h>

#define N_NODES 100000
#define E_EDGES 3200000
#define C_IN 256
#define C1 64
#define C2 40
#define SCAN_B 1024
#define NBLK ((N_NODES + SCAN_B - 1) / SCAN_B)   // 98

// ---------------- scratch (device globals; allocation-free) ----------------
__device__ __align__(16) float g_dinv[N_NODES];
__device__ __align__(16) int   g_degi[N_NODES];
__device__ __align__(16) int   g_row[N_NODES];
__device__ __align__(16) int   g_rowtmp[N_NODES];
__device__ __align__(16) int   g_cur[N_NODES];
__device__ __align__(16) int   g_bsum[NBLK];
__device__ __align__(16) int   g_boff[NBLK];
__device__ __align__(16) int2  g_edge[E_EDGES];    // CSR: {src, norm bits}
__device__ __align__(16) float g_xw1[(N_NODES + 128) * C1];
__device__ __align__(16) float g_out1[N_NODES * C1];
__device__ __align__(16) float g_xw2[N_NODES * C2];
__device__ int g_is64;

// ---------------- zero + dtype detection ------------------------------------
__global__ void k_zero_detect(const int* __restrict__ ei32) {
    int i = blockIdx.x * blockDim.x + threadIdx.x;
    if (i < N_NODES) g_degi[i] = 0;
    if (i == 0) {
        int all0 = 1;
        for (int k = 0; k < 64; k++)
            if (ei32[2 * k + 1] != 0) { all0 = 0; break; }
        g_is64 = all0;
    }
}

__device__ __forceinline__ int load_src(const int* ei32, int e) {
    return g_is64 ? ei32[2 * e] : ei32[e];
}
__device__ __forceinline__ int load_dst(const int* ei32, int e) {
    return g_is64 ? ei32[2 * (E_EDGES + e)] : ei32[E_EDGES + e];
}

// ---------------- CSR build ----------------
__global__ void k_deg_count(const int* __restrict__ ei32) {
    int e = blockIdx.x * blockDim.x + threadIdx.x;
    if (e >= E_EDGES) return;
    atomicAdd(&g_degi[load_dst(ei32, e)], 1);
}

__global__ void k_scan1_dinv() {
    __shared__ int sh[SCAN_B];
    int i = blockIdx.x * SCAN_B + threadIdx.x;
    int v = (i < N_NODES) ? g_degi[i] : 0;
    if (i < N_NODES) g_dinv[i] = rsqrtf((float)(v + 1));     // +1 self loop
    sh[threadIdx.x] = v;
    __syncthreads();
    for (int off = 1; off < SCAN_B; off <<= 1) {
        int t = (threadIdx.x >= off) ? sh[threadIdx.x - off] : 0;
        __syncthreads();
        sh[threadIdx.x] += t;
        __syncthreads();
    }
    if (i < N_NODES) g_rowtmp[i] = sh[threadIdx.x];
    if (threadIdx.x == SCAN_B - 1) g_bsum[blockIdx.x] = sh[SCAN_B - 1];
}

__global__ void k_scan2() {
    __shared__ int sh[128];
    int v = (threadIdx.x < NBLK) ? g_bsum[threadIdx.x] : 0;
    sh[threadIdx.x] = v;
    __syncthreads();
    for (int off = 1; off < 128; off <<= 1) {
        int t = (threadIdx.x >= off) ? sh[threadIdx.x - off] : 0;
        __syncthreads();
        sh[threadIdx.x] += t;
        __syncthreads();
    }
    if (threadIdx.x < NBLK) g_boff[threadIdx.x] = sh[threadIdx.x] - v;
}

__global__ void k_scan3() {
    int i = blockIdx.x * blockDim.x + threadIdx.x;
    if (i >= N_NODES) return;
    int r = g_rowtmp[i] - g_degi[i] + g_boff[i >> 10];
    g_row[i] = r;
    g_cur[i] = r;
}

__global__ void k_fill(const int* __restrict__ ei32) {
    int e = blockIdx.x * blockDim.x + threadIdx.x;
    if (e >= E_EDGES) return;
    int s = load_src(ei32, e);
    int d = load_dst(ei32, e);
    int pos = atomicAdd(&g_cur[d], 1);
    float nrm = g_dinv[s] * g_dinv[d];
    g_edge[pos] = make_int2(s, __float_as_int(nrm));
}

// ---------------- GEMM1: xw1 = x @ W1 via tf32 mma.sync --------------------
// Block: 256 threads (8 warps), tile 128 rows x 64 cols, K chunked by 32.
// Warp w computes rows w*16..w*16+15, all 64 cols (8 n-tiles of m16n8k8).
__device__ __forceinline__ uint32_t f2tf32(float f) {
    uint32_t u;
    asm("cvt.rna.tf32.f32 %0, %1;" : "=r"(u) : "f"(f));
    return u;
}

__device__ __forceinline__ void mma_tf32(float* c, const uint32_t* a,
                                         uint32_t b0, uint32_t b1) {
    asm volatile(
        "mma.sync.aligned.m16n8k8.row.col.f32.tf32.tf32.f32 "
        "{%0,%1,%2,%3}, {%4,%5,%6,%7}, {%8,%9}, {%0,%1,%2,%3};"
        : "+f"(c[0]), "+f"(c[1]), "+f"(c[2]), "+f"(c[3])
        : "r"(a[0]), "r"(a[1]), "r"(a[2]), "r"(a[3]), "r"(b0), "r"(b1));
}

#define G1_KT 32

__global__ void k_gemm1(const float* __restrict__ x, const float* __restrict__ W1) {
    __shared__ uint32_t xs[128][36];   // [row][k] tf32 bits, stride 36
    __shared__ uint32_t ws[G1_KT][68]; // [k][col] tf32 bits, stride 68
    int tid = threadIdx.x;
    int wid = tid >> 5;
    int lane = tid & 31;
    int g = lane >> 2;        // groupID 0..7
    int tcol = lane & 3;      // thread-in-group 0..3
    int rb = blockIdx.x * 128;
    int R = wid * 16;

    float c[8][4];
#pragma unroll
    for (int j = 0; j < 8; j++)
#pragma unroll
        for (int i = 0; i < 4; i++) c[j][i] = 0.0f;

    for (int kc = 0; kc < C_IN; kc += G1_KT) {
        // stage x tile (128x32) as tf32
#pragma unroll
        for (int it = 0; it < 4; it++) {
            int i = tid + 256 * it;
            int row = i >> 3;
            int k4 = (i & 7) << 2;
            int grow = rb + row;
            float4 v = make_float4(0.f, 0.f, 0.f, 0.f);
            if (grow < N_NODES)
                v = *(const float4*)(x + (long)grow * C_IN + kc + k4);
            xs[row][k4 + 0] = f2tf32(v.x);
            xs[row][k4 + 1] = f2tf32(v.y);
            xs[row][k4 + 2] = f2tf32(v.z);
            xs[row][k4 + 3] = f2tf32(v.w);
        }
        // stage W tile (32x64) as tf32
#pragma unroll
        for (int it = 0; it < 2; it++) {
            int i = tid + 256 * it;
            int wk = i >> 4;
            int wc = (i & 15) << 2;
            float4 v = *(const float4*)(W1 + (kc + wk) * C1 + wc);
            ws[wk][wc + 0] = f2tf32(v.x);
            ws[wk][wc + 1] = f2tf32(v.y);
            ws[wk][wc + 2] = f2tf32(v.z);
            ws[wk][wc + 3] = f2tf32(v.w);
        }
        __syncthreads();

#pragma unroll
        for (int kk = 0; kk < 4; kk++) {
            uint32_t a[4];
            a[0] = xs[R + g][kk * 8 + tcol];
            a[1] = xs[R + g + 8][kk * 8 + tcol];
            a[2] = xs[R + g][kk * 8 + tcol + 4];
            a[3] = xs[R + g + 8][kk * 8 + tcol + 4];
#pragma unroll
            for (int j = 0; j < 8; j++) {
                uint32_t b0 = ws[kk * 8 + tcol][j * 8 + g];
                uint32_t b1 = ws[kk * 8 + tcol + 4][j * 8 + g];
                mma_tf32(c[j], a, b0, b1);
            }
        }
        __syncthreads();
    }

    int row0 = rb + R + g;
    int row1 = row0 + 8;
#pragma unroll
    for (int j = 0; j < 8; j++) {
        int col = j * 8 + 2 * tcol;
        if (row0 < N_NODES) {
            float2 o = make_float2(c[j][0], c[j][1]);
            *(float2*)(g_xw1 + (long)row0 * C1 + col) = o;
        }
        if (row1 < N_NODES) {
            float2 o = make_float2(c[j][2], c[j][3]);
            *(float2*)(g_xw1 + (long)row1 * C1 + col) = o;
        }
    }
}

// ---------------- layer-1 aggregation: warp per node, CSR gather -----------
__global__ void k_agg1(const float* __restrict__ b1) {
    int w = (blockIdx.x * blockDim.x + threadIdx.x) >> 5;
    int lane = threadIdx.x & 31;
    if (w >= N_NODES) return;
    float dv = g_dinv[w];
    float sl = dv * dv;
    const float* xr = g_xw1 + (long)w * C1;
    float a0 = xr[lane]      * sl + b1[lane];
    float a1 = xr[32 + lane] * sl + b1[32 + lane];
    int j = g_row[w];
    int end = j + g_degi[w];

    for (; j + 8 <= end; j += 8) {
        int2 e[8];
#pragma unroll
        for (int i = 0; i < 8; i++) e[i] = g_edge[j + i];
        float v0[8], v1[8];
#pragma unroll
        for (int i = 0; i < 8; i++) {
            const float* p = g_xw1 + (long)e[i].x * C1;
            v0[i] = p[lane];
            v1[i] = p[32 + lane];
        }
#pragma unroll
        for (int i = 0; i < 8; i++) {
            float n = __int_as_float(e[i].y);
            a0 += v0[i] * n;
            a1 += v1[i] * n;
        }
    }
    for (; j < end; j++) {
        int2 e = g_edge[j];
        float nrm = __int_as_float(e.y);
        const float* p = g_xw1 + (long)e.x * C1;
        a0 += p[lane] * nrm;
        a1 += p[32 + lane] * nrm;
    }
    float* o = g_out1 + (long)w * C1;
    o[lane] = a0;
    o[32 + lane] = a1;
}

// ---------------- GEMM2: xw2 = relu(out1) @ W2 ([N,64]x[64,40]) ------------
__global__ void k_gemm2(const float* __restrict__ W2) {
    __shared__ float xs[64][68];
    __shared__ float ws[64 * 40];
    int t = threadIdx.x;
    int rb = blockIdx.x * 64;
    int r = t >> 2, q = t & 3;

    for (int i = t; i < 64 * 40; i += 256) ws[i] = W2[i];
#pragma unroll
    for (int it = 0; it < 4; it++) {
        int i = t + 256 * it;
        int rr = i >> 4, cc = (i & 15) << 2;
        int row = rb + rr;
        float4 v = make_float4(0.f, 0.f, 0.f, 0.f);
        if (row < N_NODES)
            v = *(const float4*)(g_out1 + (long)row * C1 + cc);
        v.x = fmaxf(v.x, 0.f); v.y = fmaxf(v.y, 0.f);
        v.z = fmaxf(v.z, 0.f); v.w = fmaxf(v.w, 0.f);
        *(float4*)(&xs[rr][cc]) = v;
    }
    __syncthreads();

    float acc[10];
#pragma unroll
    for (int j = 0; j < 10; j++) acc[j] = 0.0f;
#pragma unroll
    for (int k = 0; k < 64; k++) {
        float xv = xs[r][k];
#pragma unroll
        for (int j = 0; j < 10; j++)
            acc[j] += xv * ws[k * 40 + q * 10 + j];
    }
    int row = rb + r;
    if (row < N_NODES) {
#pragma unroll
        for (int j = 0; j < 10; j++)
            g_xw2[(long)row * C2 + q * 10 + j] = acc[j];
    }
}

// ---------- layer-2 aggregation + fused log_softmax: warp per node ---------
__global__ void k_agg2_lsm(const float* __restrict__ b2, float* __restrict__ out) {
    int w = (blockIdx.x * blockDim.x + threadIdx.x) >> 5;
    int lane = threadIdx.x & 31;
    if (w >= N_NODES) return;
    bool hi = (lane < 8);
    float dv = g_dinv[w];
    float sl = dv * dv;
    const float* xr = g_xw2 + (long)w * C2;
    float a0 = xr[lane] * sl + b2[lane];
    float a1 = hi ? (xr[32 + lane] * sl + b2[32 + lane]) : 0.0f;
    int j = g_row[w];
    int end = j + g_degi[w];

    for (; j + 8 <= end; j += 8) {
        int2 e[8];
#pragma unroll
        for (int i = 0; i < 8; i++) e[i] = g_edge[j + i];
        float v0[8], v1[8];
#pragma unroll
        for (int i = 0; i < 8; i++) {
            const float* p = g_xw2 + (long)e[i].x * C2;
            v0[i] = p[lane];
            v1[i] = hi ? p[32 + lane] : 0.0f;
        }
#pragma unroll
        for (int i = 0; i < 8; i++) {
            float n = __int_as_float(e[i].y);
            a0 += v0[i] * n;
            a1 += v1[i] * n;
        }
    }
    for (; j < end; j++) {
        int2 e = g_edge[j];
        float nrm = __int_as_float(e.y);
        const float* p = g_xw2 + (long)e.x * C2;
        a0 += p[lane] * nrm;
        if (hi) a1 += p[32 + lane] * nrm;
    }

    float v1 = hi ? a1 : -INFINITY;
    float m = fmaxf(a0, v1);
#pragma unroll
    for (int off = 16; off > 0; off >>= 1)
        m = fmaxf(m, __shfl_xor_sync(0xFFFFFFFFu, m, off));
    float s = expf(a0 - m) + (hi ? expf(a1 - m) : 0.0f);
#pragma unroll
    for (int off = 16; off > 0; off >>= 1)
        s += __shfl_xor_sync(0xFFFFFFFFu, s, off);
    float lse = m + logf(s);
    float* o = out + (long)w * C2;
    o[lane] = a0 - lse;
    if (hi) o[32 + lane] = a1 - lse;
}

// ---------------- launch: fork CSR build alongside GEMM1 --------------------
extern "C" void kernel_launch(void* const* d_in, const int* in_sizes, int n_in,
                              void* d_out, int out_size) {
    const float* x   = (const float*)d_in[0];
    const int*   ei  = (const int*)d_in[1];
    const float* W1  = (const float*)d_in[2];
    const float* b1  = (const float*)d_in[3];
    const float* W2  = (const float*)d_in[4];
    const float* b2  = (const float*)d_in[5];
    float* out = (float*)d_out;

    const int TB = 256;

    static cudaStream_t s_csr = nullptr;
    static cudaEvent_t ev_fork = nullptr, ev_join = nullptr;
    if (s_csr == nullptr) {
        cudaStreamCreateWithFlags(&s_csr, cudaStreamNonBlocking);
        cudaEventCreateWithFlags(&ev_fork, cudaEventDisableTiming);
        cudaEventCreateWithFlags(&ev_join, cudaEventDisableTiming);
    }

    cudaEventRecord(ev_fork, 0);
    cudaStreamWaitEvent(s_csr, ev_fork, 0);

    k_zero_detect<<<(N_NODES + TB - 1) / TB, TB, 0, s_csr>>>(ei);
    k_deg_count<<<(E_EDGES + TB - 1) / TB, TB, 0, s_csr>>>(ei);
    k_scan1_dinv<<<NBLK, SCAN_B, 0, s_csr>>>();
    k_scan2<<<1, 128, 0, s_csr>>>();
    k_scan3<<<(N_NODES + TB - 1) / TB, TB, 0, s_csr>>>();
    k_fill<<<(E_EDGES + TB - 1) / TB, TB, 0, s_csr>>>(ei);
    cudaEventRecord(ev_join, s_csr);

    k_gemm1<<<(N_NODES + 127) / 128, 256>>>(x, W1);

    cudaStreamWaitEvent(0, ev_join, 0);

    k_agg1<<<(N_NODES * 32 + TB - 1) / TB, TB>>>(b1);
    k_gemm2<<<(N_NODES + 63) / 64, 256>>>(W2);
    k_agg2_lsm<<<(N_NODES * 32 + TB - 1) / TB, TB>>>(b2, out);
}